// round 12
// baseline (speedup 1.0000x reference)
#include <cuda_runtime.h>
#include <cuda_bf16.h>
#include <cstdint>

// Problem constants (fixed shapes from reference setup_inputs)
#define NN 50000      // nodes
#define FF 128        // F_in == H
#define OO 64         // output feature dim
#define EE 800000     // edges per relation (and neg edges)
#define NSEG (2 * NN) // (relation, node) segments
#define NB_SCAN ((NSEG + 1023) / 1024)   // 98 blocks

// ---------------- scratch (device globals; device-code access ONLY) --------
__device__ alignas(16) float g_agg0[NN * FF];      // layer-1 means (128-wide)
__device__ alignas(16) float g_agg1[NN * FF];
__device__ alignas(16) float g_h1[NN * FF];        // layer 1 output
__device__ alignas(16) float g_Y[NN * FF];         // h1 @ [Wn2_0 | Wn2_1]
__device__ alignas(16) float g_h2[NN * OO];        // h2part then final h2
__device__ alignas(16) float g_W1[384 * 128];      // packed [Wself_sum; Wn0; Wn1]
__device__ alignas(16) float g_b1[128];
__device__ alignas(16) float g_W23[128 * 192];     // [Ws2sum | Wn2_0 | Wn2_1]
__device__ alignas(16) float g_b2[64];
// CSR structures (built once, used by both layers)
__device__ int g_deg[NSEG];
__device__ int g_off[NSEG];
__device__ int g_cursor[NSEG];
__device__ int g_bsum[NB_SCAN];
__device__ int g_csr[2 * EE];

// ---------------- packed fp32x2 helpers (Blackwell FFMA2 path) --------------
__device__ __forceinline__ unsigned long long dup2(float a) {
    unsigned long long r;
    asm("mov.b64 %0, {%1, %1};" : "=l"(r) : "f"(a));
    return r;
}
__device__ __forceinline__ unsigned long long fma2(unsigned long long a,
                                                   unsigned long long b,
                                                   unsigned long long c) {
    unsigned long long d;
    asm("fma.rn.f32x2 %0, %1, %2, %3;" : "=l"(d) : "l"(a), "l"(b), "l"(c));
    return d;
}
__device__ __forceinline__ void unpack2(unsigned long long p, float& lo, float& hi) {
    asm("mov.b64 {%0, %1}, %2;" : "=f"(lo), "=f"(hi) : "l"(p));
}

// ---------------- CSR build -------------------------------------------------
__global__ void zero_deg_kernel() {
    int i = blockIdx.x * blockDim.x + threadIdx.x;
    if (i < NSEG) g_deg[i] = 0;
}

__global__ void deg_kernel(const int* __restrict__ edges) {
    int i = blockIdx.x * blockDim.x + threadIdx.x;
    if (i < 2 * EE) {
        int r = i / EE;
        int e = i - r * EE;
        int dst = edges[r * 2 * EE + EE + e];
        atomicAdd(&g_deg[r * NN + dst], 1);
    }
}

__global__ void scanA_kernel() {
    __shared__ int sh[1024];
    int gid = blockIdx.x * 1024 + threadIdx.x;
    int v = (gid < NSEG) ? g_deg[gid] : 0;
    sh[threadIdx.x] = v;
    __syncthreads();
    for (int off = 1; off < 1024; off <<= 1) {
        int t = (threadIdx.x >= off) ? sh[threadIdx.x - off] : 0;
        __syncthreads();
        sh[threadIdx.x] += t;
        __syncthreads();
    }
    int incl = sh[threadIdx.x];
    if (gid < NSEG) g_off[gid] = incl - v;
    if (threadIdx.x == 1023) g_bsum[blockIdx.x] = incl;
}

__global__ void scanBC_kernel() {
    __shared__ int sh[NB_SCAN];
    int t = threadIdx.x;
    int v0 = 0;
    if (t < NB_SCAN) { v0 = g_bsum[t]; sh[t] = v0; }
    __syncthreads();
    for (int off = 1; off < NB_SCAN; off <<= 1) {
        int v = (t >= off && t < NB_SCAN) ? sh[t - off] : 0;
        __syncthreads();
        if (t < NB_SCAN) sh[t] += v;
        __syncthreads();
    }
    if (t < NB_SCAN) sh[t] -= v0;   // exclusive
    __syncthreads();
    int gid = blockIdx.x * blockDim.x + t;
    if (gid < NSEG) {
        int o = g_off[gid] + sh[gid >> 10];
        g_off[gid] = o;
        g_cursor[gid] = o;
    }
}

__global__ void fill_kernel(const int* __restrict__ edges) {
    int i = blockIdx.x * blockDim.x + threadIdx.x;
    if (i < 2 * EE) {
        int r = i / EE;
        int e = i - r * EE;
        const int* ed = edges + r * 2 * EE;
        int src = ed[e];
        int dst = ed[EE + e];
        int pos = atomicAdd(&g_cursor[r * NN + dst], 1);
        g_csr[pos] = src;
    }
}

// ---------------- weight packing --------------------------------------------
__global__ void pack1_kernel(const float* __restrict__ Wself,
                             const float* __restrict__ Wneigh,
                             const float* __restrict__ b) {
    int idx = blockIdx.x * blockDim.x + threadIdx.x;
    if (idx < 384 * 128) {
        int k = idx >> 7;
        int n = idx & 127;
        float w;
        if (k < 128)      w = Wself[k * 128 + n] + Wself[128 * 128 + k * 128 + n];
        else if (k < 256) w = Wneigh[(k - 128) * 128 + n];
        else              w = Wneigh[128 * 128 + (k - 256) * 128 + n];
        g_W1[idx] = w;
    }
    if (idx < 128) g_b1[idx] = b[idx] + b[128 + idx];
}

// W23 = [Ws2sum(64) | Wn2_0(64) | Wn2_1(64)] : 128 x 192
__global__ void pack23_kernel(const float* __restrict__ Wself,
                              const float* __restrict__ Wneigh,
                              const float* __restrict__ b) {
    int idx = blockIdx.x * blockDim.x + threadIdx.x;
    if (idx < 128 * 192) {
        int k = idx / 192;
        int n = idx - k * 192;
        float w;
        if (n < 64)       w = Wself[k * 64 + n] + Wself[128 * 64 + k * 64 + n];
        else if (n < 128) w = Wneigh[k * 64 + (n - 64)];
        else              w = Wneigh[128 * 64 + k * 64 + (n - 128)];
        g_W23[idx] = w;
    }
    if (idx < 64) g_b2[idx] = b[idx] + b[64 + idx];
}

// ---------------- CSR gather (layer 1) ---------------------------------------
__global__ void gather1_kernel(const float* __restrict__ x) {
    int gw = (blockIdx.x * blockDim.x + threadIdx.x) >> 5;
    int lane = threadIdx.x & 31;
    if (gw >= NSEG) return;
    int r = gw >= NN;
    int node = gw - r * NN;
    int start = g_off[gw];
    int cnt = g_deg[gw];
    float4 acc = make_float4(0.f, 0.f, 0.f, 0.f);
    for (int k = 0; k < cnt; ++k) {
        int src = __ldg(&g_csr[start + k]);
        float4 v = *reinterpret_cast<const float4*>(x + (size_t)src * FF + lane * 4);
        acc.x += v.x; acc.y += v.y; acc.z += v.z; acc.w += v.w;
    }
    float sc = 1.0f / fmaxf((float)cnt, 1.0f);
    acc.x *= sc; acc.y *= sc; acc.z *= sc; acc.w *= sc;
    float* agg = r ? g_agg1 : g_agg0;
    *reinterpret_cast<float4*>(agg + (size_t)node * FF + lane * 4) = acc;
}

// ---------------- layer-1 GEMM (K=384, N=128) --------------------------------
// h1 = relu([x | mean0 | mean1] @ W1 + b1)
__global__ void __launch_bounds__(256) gemm1_k(const float* __restrict__ x) {
    constexpr int BN = 128, BK = 32, TM = 8, TN = 8, TN2 = 4;

    __shared__ alignas(16) float As[BK][128 + 4];
    __shared__ alignas(16) float Bs[BK][BN];

    int tid = threadIdx.x;
    int m0 = blockIdx.x * 128;
    int tx = tid & 15;
    int ty = tid >> 4;

    unsigned long long acc2[TM][TN2];
#pragma unroll
    for (int i = 0; i < TM; i++)
#pragma unroll
        for (int j = 0; j < TN2; j++) acc2[i][j] = 0ull;

#pragma unroll 1
    for (int t = 0; t < 12; ++t) {
        int kg = t * BK;
        int slice = kg >> 7;
        const float* Ap = (slice == 0) ? x : ((slice == 1) ? g_agg0 : g_agg1);
        int koff = kg & 127;

#pragma unroll
        for (int i = 0; i < 4; ++i) {
            int idx = tid + i * 256;
            int row = idx >> 3;
            int c4 = idx & 7;
            float4 v = make_float4(0.f, 0.f, 0.f, 0.f);
            int gm = m0 + row;
            if (gm < NN)
                v = *reinterpret_cast<const float4*>(Ap + (size_t)gm * 128 + koff + c4 * 4);
            As[c4 * 4 + 0][row] = v.x;
            As[c4 * 4 + 1][row] = v.y;
            As[c4 * 4 + 2][row] = v.z;
            As[c4 * 4 + 3][row] = v.w;
        }
#pragma unroll
        for (int i = 0; i < 4; ++i) {
            int idx = tid + i * 256;
            int kk = idx >> 5;
            int n4 = idx & 31;
            *reinterpret_cast<float4*>(&Bs[kk][n4 * 4]) =
                *reinterpret_cast<const float4*>(g_W1 + (size_t)(kg + kk) * BN + n4 * 4);
        }
        __syncthreads();

#pragma unroll
        for (int kk = 0; kk < BK; ++kk) {
            const float4* Ar = reinterpret_cast<const float4*>(&As[kk][ty * TM]);
            float4 a0 = Ar[0], a1 = Ar[1];
            unsigned long long ad[TM];
            ad[0] = dup2(a0.x); ad[1] = dup2(a0.y); ad[2] = dup2(a0.z); ad[3] = dup2(a0.w);
            ad[4] = dup2(a1.x); ad[5] = dup2(a1.y); ad[6] = dup2(a1.z); ad[7] = dup2(a1.w);
            const double2* Br = reinterpret_cast<const double2*>(&Bs[kk][tx * TN]);
            double2 bq0 = Br[0], bq1 = Br[1];
            unsigned long long bp[TN2];
            bp[0] = __double_as_longlong(bq0.x);
            bp[1] = __double_as_longlong(bq0.y);
            bp[2] = __double_as_longlong(bq1.x);
            bp[3] = __double_as_longlong(bq1.y);
#pragma unroll
            for (int i = 0; i < TM; i++)
#pragma unroll
                for (int j = 0; j < TN2; j++)
                    acc2[i][j] = fma2(ad[i], bp[j], acc2[i][j]);
        }
        __syncthreads();
    }

#pragma unroll
    for (int i = 0; i < TM; i++) {
        int gm = m0 + ty * TM + i;
        if (gm >= NN) continue;
        float accs[TN];
#pragma unroll
        for (int j = 0; j < TN2; j++) unpack2(acc2[i][j], accs[2 * j], accs[2 * j + 1]);
#pragma unroll
        for (int j = 0; j < TN; j++) {
            int gn = tx * TN + j;
            g_h1[(size_t)gm * 128 + gn] = fmaxf(accs[j] + g_b1[gn], 0.f);
        }
    }
}

// ---------------- layer-2 merged GEMM (K=128, N=192) -------------------------
// [h2part | Y] = h1 @ W23  (+b2 on first 64 cols)
__global__ void __launch_bounds__(256) gemm23_k() {
    constexpr int BN = 192, BK = 32, TM = 8, TN = 12, TN2 = 6;

    __shared__ alignas(16) float As[BK][128 + 4];
    __shared__ alignas(16) float Bs[BK][BN];

    int tid = threadIdx.x;
    int m0 = blockIdx.x * 128;
    int tx = tid & 15;                 // 16 groups * 12 cols = 192
    int ty = tid >> 4;

    unsigned long long acc2[TM][TN2];
#pragma unroll
    for (int i = 0; i < TM; i++)
#pragma unroll
        for (int j = 0; j < TN2; j++) acc2[i][j] = 0ull;

    int brow = tid >> 3;               // 0..31
    int bcol = (tid & 7) * 24;         // 0..168

#pragma unroll 1
    for (int t = 0; t < 4; ++t) {
        int kg = t * BK;

#pragma unroll
        for (int i = 0; i < 4; ++i) {
            int idx = tid + i * 256;
            int row = idx >> 3;
            int c4 = idx & 7;
            float4 v = make_float4(0.f, 0.f, 0.f, 0.f);
            int gm = m0 + row;
            if (gm < NN)
                v = *reinterpret_cast<const float4*>(g_h1 + (size_t)gm * 128 + kg + c4 * 4);
            As[c4 * 4 + 0][row] = v.x;
            As[c4 * 4 + 1][row] = v.y;
            As[c4 * 4 + 2][row] = v.z;
            As[c4 * 4 + 3][row] = v.w;
        }
#pragma unroll
        for (int q = 0; q < 6; q++) {
            *reinterpret_cast<float4*>(&Bs[brow][bcol + q * 4]) =
                *reinterpret_cast<const float4*>(g_W23 + (size_t)(kg + brow) * BN + bcol + q * 4);
        }
        __syncthreads();

#pragma unroll
        for (int kk = 0; kk < BK; ++kk) {
            const float4* Ar = reinterpret_cast<const float4*>(&As[kk][ty * TM]);
            float4 a0 = Ar[0], a1 = Ar[1];
            unsigned long long ad[TM];
            ad[0] = dup2(a0.x); ad[1] = dup2(a0.y); ad[2] = dup2(a0.z); ad[3] = dup2(a0.w);
            ad[4] = dup2(a1.x); ad[5] = dup2(a1.y); ad[6] = dup2(a1.z); ad[7] = dup2(a1.w);
            const double2* Br = reinterpret_cast<const double2*>(&Bs[kk][tx * TN]);
            double2 bq0 = Br[0], bq1 = Br[1], bq2 = Br[2];
            unsigned long long bp[TN2];
            bp[0] = __double_as_longlong(bq0.x);
            bp[1] = __double_as_longlong(bq0.y);
            bp[2] = __double_as_longlong(bq1.x);
            bp[3] = __double_as_longlong(bq1.y);
            bp[4] = __double_as_longlong(bq2.x);
            bp[5] = __double_as_longlong(bq2.y);
#pragma unroll
            for (int i = 0; i < TM; i++)
#pragma unroll
                for (int j = 0; j < TN2; j++)
                    acc2[i][j] = fma2(ad[i], bp[j], acc2[i][j]);
        }
        __syncthreads();
    }

#pragma unroll
    for (int i = 0; i < TM; i++) {
        int gm = m0 + ty * TM + i;
        if (gm >= NN) continue;
        float accs[TN];
#pragma unroll
        for (int j = 0; j < TN2; j++) unpack2(acc2[i][j], accs[2 * j], accs[2 * j + 1]);
        int j0 = tx * TN;
#pragma unroll
        for (int j = 0; j < TN; j++) {
            int col = j0 + j;
            if (col < 64)
                g_h2[(size_t)gm * OO + col] = accs[j] + g_b2[col];
            else
                g_Y[(size_t)gm * FF + (col - 64)] = accs[j];
        }
    }
}

// ---------------- layer-2 gather: per-node, both relations, finalize h2 -----
__global__ void gather2f_kernel() {
    int t = blockIdx.x * blockDim.x + threadIdx.x;
    int node = t >> 4;
    int lane = t & 15;
    if (node >= NN) return;
    float4 acc0 = make_float4(0.f, 0.f, 0.f, 0.f);
    {
        int start = g_off[node];
        int cnt = g_deg[node];
        for (int k = 0; k < cnt; ++k) {
            int src = __ldg(&g_csr[start + k]);
            float4 v = *reinterpret_cast<const float4*>(g_Y + (size_t)src * FF + lane * 4);
            acc0.x += v.x; acc0.y += v.y; acc0.z += v.z; acc0.w += v.w;
        }
        float sc = 1.0f / fmaxf((float)cnt, 1.0f);
        acc0.x *= sc; acc0.y *= sc; acc0.z *= sc; acc0.w *= sc;
    }
    float4 acc1 = make_float4(0.f, 0.f, 0.f, 0.f);
    {
        int start = g_off[NN + node];
        int cnt = g_deg[NN + node];
        for (int k = 0; k < cnt; ++k) {
            int src = __ldg(&g_csr[start + k]);
            float4 v = *reinterpret_cast<const float4*>(g_Y + (size_t)src * FF + 64 + lane * 4);
            acc1.x += v.x; acc1.y += v.y; acc1.z += v.z; acc1.w += v.w;
        }
        float sc = 1.0f / fmaxf((float)cnt, 1.0f);
        acc1.x *= sc; acc1.y *= sc; acc1.z *= sc; acc1.w *= sc;
    }
    float4 h = *reinterpret_cast<const float4*>(g_h2 + (size_t)node * OO + lane * 4);
    h.x += acc0.x + acc1.x;
    h.y += acc0.y + acc1.y;
    h.z += acc0.z + acc1.z;
    h.w += acc0.w + acc1.w;
    *reinterpret_cast<float4*>(g_h2 + (size_t)node * OO + lane * 4) = h;
}

// ---------------- edge scoring (16 lanes per edge, float4) ------------------
__global__ void score_kernel(const int* __restrict__ edges,
                             const int* __restrict__ neg,
                             float* __restrict__ out, int out_n) {
    int t = blockIdx.x * blockDim.x + threadIdx.x;
    int ge = t >> 4;
    int lane = t & 15;
    if (ge >= 2 * EE) return;
    int u, v;
    if (ge < EE) { u = edges[ge]; v = edges[EE + ge]; }
    else { int e = ge - EE; u = neg[e]; v = neg[EE + e]; }
    float4 a = *reinterpret_cast<const float4*>(g_h2 + (size_t)u * OO + lane * 4);
    float4 b = *reinterpret_cast<const float4*>(g_h2 + (size_t)v * OO + lane * 4);
    float s = a.x * b.x + a.y * b.y + a.z * b.z + a.w * b.w;
#pragma unroll
    for (int off = 8; off; off >>= 1) s += __shfl_xor_sync(0xffffffffu, s, off);
    if (lane == 0 && ge < out_n) out[ge] = s;
}

// ---------------- launch ----------------------------------------------------
extern "C" void kernel_launch(void* const* d_in, const int* in_sizes, int n_in,
                              void* d_out, int out_size) {
    // Resolve inputs by element count; positional fallback (reference order).
    const float* x = nullptr;  const int* edges = nullptr; const int* neg = nullptr;
    const float* Wneigh1 = nullptr, *Wself1 = nullptr, *b1 = nullptr;
    const float* Wneigh2 = nullptr, *Wself2 = nullptr, *b2 = nullptr;
    {
        const float* wn1 = nullptr, *ws1 = nullptr, *wn2 = nullptr, *ws2 = nullptr;
        const float* xx = nullptr, *bb1 = nullptr, *bb2 = nullptr;
        const int* ee = nullptr, *nn = nullptr;
        for (int i = 0; i < n_in; ++i) {
            long s = in_sizes[i];
            const void* p = d_in[i];
            if      (s == (long)NN * FF)       xx = (const float*)p;
            else if (s == (long)2 * 2 * EE)    ee = (const int*)p;
            else if (s == (long)2 * EE)        nn = (const int*)p;
            else if (s == (long)2 * 128 * 128) { if (!wn1) wn1 = (const float*)p; else ws1 = (const float*)p; }
            else if (s == (long)2 * 128)       bb1 = (const float*)p;
            else if (s == (long)2 * 128 * 64)  { if (!wn2) wn2 = (const float*)p; else ws2 = (const float*)p; }
            else if (s == (long)2 * 64)        bb2 = (const float*)p;
        }
        if (xx && ee && nn && wn1 && ws1 && bb1 && wn2 && ws2 && bb2) {
            x = xx; edges = ee; neg = nn;
            Wneigh1 = wn1; Wself1 = ws1; b1 = bb1;
            Wneigh2 = wn2; Wself2 = ws2; b2 = bb2;
        }
    }
    if (!x) {
        x       = (const float*)d_in[0];
        edges   = (const int*)  d_in[1];
        neg     = (const int*)  d_in[2];
        Wneigh1 = (const float*)d_in[3];
        Wself1  = (const float*)d_in[4];
        b1      = (const float*)d_in[5];
        Wneigh2 = (const float*)d_in[6];
        Wself2  = (const float*)d_in[7];
        b2      = (const float*)d_in[8];
    }
    float* out = (float*)d_out;
    int out_n = out_size;
    if (out_n > 2 * EE) out_n = 2 * EE;

    int edgeBlocks    = (2 * EE + 255) / 256;
    int segBlocks     = (NSEG + 255) / 256;
    int gather1Blocks = (NSEG * 32 + 255) / 256;
    int gather2Blocks = (NN * 16 + 255) / 256;
    int gemmBlocks    = (NN + 127) / 128;
    int scoreBlocks   = (2 * EE * 16 + 255) / 256;

    // CSR build (used by both layers)
    zero_deg_kernel<<<segBlocks, 256>>>();                                // 1
    deg_kernel<<<edgeBlocks, 256>>>(edges);                               // 2
    scanA_kernel<<<NB_SCAN, 1024>>>();                                    // 3
    scanBC_kernel<<<segBlocks, 256>>>();                                  // 4
    fill_kernel<<<edgeBlocks, 256>>>(edges);                              // 5
    gather1_kernel<<<gather1Blocks, 256>>>(x);                            // 6

    // packed weights
    pack1_kernel<<<(384 * 128 + 255) / 256, 256>>>(Wself1, Wneigh1, b1);  // 7
    pack23_kernel<<<(128 * 192 + 255) / 256, 256>>>(Wself2, Wneigh2, b2); // 8

    // layer-1 GEMM (separate kernel; preserves occupancy/overlap)
    gemm1_k<<<gemmBlocks, 256>>>(x);                                      // 9

    // layer-2 merged projection: [h2part | Y] = h1 @ W23 (h1 read once)
    gemm23_k<<<gemmBlocks, 256>>>();                                      // 10

    // layer-2 gather + h2 finalize (no agg round-trip)
    gather2f_kernel<<<gather2Blocks, 256>>>();                            // 11

    // scoring
    score_kernel<<<scoreBlocks, 256>>>(edges, neg, out, out_n);           // 12
}

// round 13
// speedup vs baseline: 1.0987x; 1.0987x over previous
#include <cuda_runtime.h>
#include <cuda_bf16.h>
#include <cstdint>

// Problem constants (fixed shapes from reference setup_inputs)
#define NN 50000      // nodes
#define FF 128        // F_in == H
#define OO 64         // output feature dim
#define EE 800000     // edges per relation (and neg edges)
#define NSEG (2 * NN) // (relation, node) segments
#define NB_SCAN ((NSEG + 1023) / 1024)   // 98 blocks

// ---------------- scratch (device globals; device-code access ONLY) --------
__device__ alignas(16) float g_agg0[NN * FF];      // layer1: mean 128-wide; layer2: 64-wide
__device__ alignas(16) float g_agg1[NN * FF];
__device__ alignas(16) float g_h1[NN * FF];        // layer 1 output
__device__ alignas(16) float g_Y[NN * FF];         // h1 @ [Wn2_0 | Wn2_1]
__device__ alignas(16) float g_h2[NN * OO];        // layer 2 output
__device__ alignas(16) float g_W1[384 * 128];      // packed [Wself_sum; Wn0; Wn1]
__device__ alignas(16) float g_b1[128];
__device__ alignas(16) float g_Wn2pack[128 * 128]; // [Wn2_0 | Wn2_1]
__device__ alignas(16) float g_Ws2sum[128 * 64];   // Wself2[0]+Wself2[1]
__device__ alignas(16) float g_b2[64];
// CSR structures (built once, used by both layers)
__device__ int g_deg[NSEG];
__device__ int g_off[NSEG];
__device__ int g_cursor[NSEG];
__device__ int g_bsum[NB_SCAN];
__device__ int g_csr[2 * EE];

// ---------------- packed fp32x2 helpers (Blackwell FFMA2 path) --------------
__device__ __forceinline__ unsigned long long dup2(float a) {
    unsigned long long r;
    asm("mov.b64 %0, {%1, %1};" : "=l"(r) : "f"(a));
    return r;
}
__device__ __forceinline__ unsigned long long fma2(unsigned long long a,
                                                   unsigned long long b,
                                                   unsigned long long c) {
    unsigned long long d;
    asm("fma.rn.f32x2 %0, %1, %2, %3;" : "=l"(d) : "l"(a), "l"(b), "l"(c));
    return d;
}
__device__ __forceinline__ void unpack2(unsigned long long p, float& lo, float& hi) {
    asm("mov.b64 {%0, %1}, %2;" : "=f"(lo), "=f"(hi) : "l"(p));
}

// ---------------- CSR build -------------------------------------------------
__global__ void zero_deg_kernel() {
    int i = blockIdx.x * blockDim.x + threadIdx.x;
    if (i < NSEG) g_deg[i] = 0;
}

__global__ void deg_kernel(const int* __restrict__ edges) {
    int i = blockIdx.x * blockDim.x + threadIdx.x;
    if (i < 2 * EE) {
        int r = i / EE;
        int e = i - r * EE;
        int dst = edges[r * 2 * EE + EE + e];
        atomicAdd(&g_deg[r * NN + dst], 1);
    }
}

// block-wise exclusive scan (1024/block) producing per-block sums
__global__ void scanA_kernel() {
    __shared__ int sh[1024];
    int gid = blockIdx.x * 1024 + threadIdx.x;
    int v = (gid < NSEG) ? g_deg[gid] : 0;
    sh[threadIdx.x] = v;
    __syncthreads();
    for (int off = 1; off < 1024; off <<= 1) {
        int t = (threadIdx.x >= off) ? sh[threadIdx.x - off] : 0;
        __syncthreads();
        sh[threadIdx.x] += t;
        __syncthreads();
    }
    int incl = sh[threadIdx.x];
    if (gid < NSEG) g_off[gid] = incl - v;
    if (threadIdx.x == 1023) g_bsum[blockIdx.x] = incl;
}

// fused: every block redundantly exclusive-scans the 98 block sums in shared,
// then applies the cross-block offset
__global__ void scanBC_kernel() {
    __shared__ int sh[NB_SCAN];
    int t = threadIdx.x;
    int v0 = 0;
    if (t < NB_SCAN) { v0 = g_bsum[t]; sh[t] = v0; }
    __syncthreads();
    for (int off = 1; off < NB_SCAN; off <<= 1) {
        int v = (t >= off && t < NB_SCAN) ? sh[t - off] : 0;
        __syncthreads();
        if (t < NB_SCAN) sh[t] += v;
        __syncthreads();
    }
    if (t < NB_SCAN) sh[t] -= v0;   // exclusive
    __syncthreads();
    int gid = blockIdx.x * blockDim.x + t;
    if (gid < NSEG) {
        int o = g_off[gid] + sh[gid >> 10];
        g_off[gid] = o;
        g_cursor[gid] = o;
    }
}

__global__ void fill_kernel(const int* __restrict__ edges) {
    int i = blockIdx.x * blockDim.x + threadIdx.x;
    if (i < 2 * EE) {
        int r = i / EE;
        int e = i - r * EE;
        const int* ed = edges + r * 2 * EE;
        int src = ed[e];
        int dst = ed[EE + e];
        int pos = atomicAdd(&g_cursor[r * NN + dst], 1);
        g_csr[pos] = src;
    }
}

// ---------------- weight packing (both layers, single launch) ----------------
__global__ void pack_all_kernel(const float* __restrict__ Wself1,
                                const float* __restrict__ Wneigh1,
                                const float* __restrict__ b1,
                                const float* __restrict__ Wself2,
                                const float* __restrict__ Wneigh2,
                                const float* __restrict__ b2) {
    int idx = blockIdx.x * blockDim.x + threadIdx.x;
    // layer 1: W1 = [Wself1_sum; Wn1_0; Wn1_1]  (384 x 128)
    if (idx < 384 * 128) {
        int k = idx >> 7;
        int n = idx & 127;
        float w;
        if (k < 128)      w = Wself1[k * 128 + n] + Wself1[128 * 128 + k * 128 + n];
        else if (k < 256) w = Wneigh1[(k - 128) * 128 + n];
        else              w = Wneigh1[128 * 128 + (k - 256) * 128 + n];
        g_W1[idx] = w;
    }
    // layer 2 packs (disjoint index ranges within the same grid)
    if (idx < 128 * 128) {
        int k = idx >> 7;
        int n = idx & 127;
        g_Wn2pack[idx] = (n < 64) ? Wneigh2[k * 64 + n]
                                  : Wneigh2[128 * 64 + k * 64 + (n - 64)];
    }
    if (idx < 128 * 64) g_Ws2sum[idx] = Wself2[idx] + Wself2[128 * 64 + idx];
    if (idx < 128)      g_b1[idx] = b1[idx] + b1[128 + idx];
    if (idx < 64)       g_b2[idx] = b2[idx] + b2[64 + idx];
}

// ---------------- CSR gather (no atomics, writes means directly) ------------
// layer 1: warp per (relation, node); 128-wide rows of x
__global__ void gather1_kernel(const float* __restrict__ x) {
    int gw = (blockIdx.x * blockDim.x + threadIdx.x) >> 5;
    int lane = threadIdx.x & 31;
    if (gw >= NSEG) return;
    int r = gw >= NN;
    int node = gw - r * NN;
    int start = g_off[gw];
    int cnt = g_deg[gw];
    float4 acc = make_float4(0.f, 0.f, 0.f, 0.f);
    for (int k = 0; k < cnt; ++k) {
        int src = __ldg(&g_csr[start + k]);
        float4 v = *reinterpret_cast<const float4*>(x + (size_t)src * FF + lane * 4);
        acc.x += v.x; acc.y += v.y; acc.z += v.z; acc.w += v.w;
    }
    float sc = 1.0f / fmaxf((float)cnt, 1.0f);
    acc.x *= sc; acc.y *= sc; acc.z *= sc; acc.w *= sc;
    float* agg = r ? g_agg1 : g_agg0;
    *reinterpret_cast<float4*>(agg + (size_t)node * FF + lane * 4) = acc;
}

// layer 2: 16 lanes per (relation, node); 64-wide slices of Y
__global__ void gather2_kernel() {
    int t = blockIdx.x * blockDim.x + threadIdx.x;
    int grp = t >> 4;
    int lane = t & 15;
    if (grp >= NSEG) return;
    int r = grp >= NN;
    int node = grp - r * NN;
    int start = g_off[grp];
    int cnt = g_deg[grp];
    float4 acc = make_float4(0.f, 0.f, 0.f, 0.f);
    const float* Ysl = g_Y + r * OO;
    for (int k = 0; k < cnt; ++k) {
        int src = __ldg(&g_csr[start + k]);
        float4 v = *reinterpret_cast<const float4*>(Ysl + (size_t)src * FF + lane * 4);
        acc.x += v.x; acc.y += v.y; acc.z += v.z; acc.w += v.w;
    }
    float sc = 1.0f / fmaxf((float)cnt, 1.0f);
    acc.x *= sc; acc.y *= sc; acc.z *= sc; acc.w *= sc;
    float* agg = r ? g_agg1 : g_agg0;
    *reinterpret_cast<float4*>(agg + (size_t)node * OO + lane * 4) = acc;
}

// ---------------- GEMM core (3 modes), packed-f32x2 mainloop ----------------
// MODE 1: h1 = relu([x | mean0 | mean1] @ W1 + b1)     (K=384, N=128)
// MODE 3: Y  = h1 @ Wn2pack                            (K=128, N=128)
// MODE 2: h2 = h1 @ Ws2sum + b2 + mean0 + mean1        (K=128, N=64)
template <int MODE>
__global__ void __launch_bounds__(256) gemm_k(const float* __restrict__ x) {
    constexpr int N  = (MODE == 2) ? 64 : 128;
    constexpr int BN = N;
    constexpr int TN = N / 16;          // 8 or 4
    constexpr int TN2 = TN / 2;         // packed accumulators along n
    constexpr int BM = 128, BK = 32, TM = 8;
    constexpr int KT = (MODE == 1) ? 12 : 4;
    constexpr int M = NN;

    __shared__ alignas(16) float As[BK][BM + 4];
    __shared__ alignas(16) float Bs[BK][BN];

    const float* A0 = (MODE == 1) ? x : g_h1;
    const float* W  = (MODE == 1) ? g_W1 : ((MODE == 3) ? g_Wn2pack : g_Ws2sum);
    float* C        = (MODE == 1) ? g_h1 : ((MODE == 3) ? g_Y : g_h2);

    int tid = threadIdx.x;
    int m0 = blockIdx.x * BM;
    int tx = tid % (BN / TN);
    int ty = tid / (BN / TN);

    unsigned long long acc2[TM][TN2];
#pragma unroll
    for (int i = 0; i < TM; i++)
#pragma unroll
        for (int j = 0; j < TN2; j++) acc2[i][j] = 0ull;

#pragma unroll 1
    for (int t = 0; t < KT; ++t) {
        int kg = t * BK;
        const float* Ap;
        int koff;
        if (MODE == 1) {
            int slice = kg >> 7;
            Ap = (slice == 0) ? A0 : ((slice == 1) ? g_agg0 : g_agg1);
            koff = kg & 127;
        } else {
            Ap = A0;
            koff = kg;
        }

        // A tile: 128x32 transposed into As[k][m]
#pragma unroll
        for (int i = 0; i < 4; ++i) {
            int idx = tid + i * 256;
            int row = idx >> 3;
            int c4 = idx & 7;
            float4 v = make_float4(0.f, 0.f, 0.f, 0.f);
            int gm = m0 + row;
            if (gm < M)
                v = *reinterpret_cast<const float4*>(Ap + (size_t)gm * 128 + koff + c4 * 4);
            As[c4 * 4 + 0][row] = v.x;
            As[c4 * 4 + 1][row] = v.y;
            As[c4 * 4 + 2][row] = v.z;
            As[c4 * 4 + 3][row] = v.w;
        }
        // B tile: 32 x BN
#pragma unroll
        for (int i = 0; i < BN / 32; ++i) {
            int idx = tid + i * 256;
            int kk = idx / (BN / 4);
            int n4 = idx - kk * (BN / 4);
            float4 v = *reinterpret_cast<const float4*>(W + (size_t)(kg + kk) * N + n4 * 4);
            *reinterpret_cast<float4*>(&Bs[kk][n4 * 4]) = v;
        }
        __syncthreads();

#pragma unroll
        for (int kk = 0; kk < BK; ++kk) {
            const float4* Ar = reinterpret_cast<const float4*>(&As[kk][ty * TM]);
            float4 a0 = Ar[0], a1 = Ar[1];
            unsigned long long ad[TM];
            ad[0] = dup2(a0.x); ad[1] = dup2(a0.y); ad[2] = dup2(a0.z); ad[3] = dup2(a0.w);
            ad[4] = dup2(a1.x); ad[5] = dup2(a1.y); ad[6] = dup2(a1.z); ad[7] = dup2(a1.w);
            const double2* Br = reinterpret_cast<const double2*>(&Bs[kk][tx * TN]);
            unsigned long long bp[TN2];
            {
                double2 bq = Br[0];
                bp[0] = __double_as_longlong(bq.x);
                bp[1] = __double_as_longlong(bq.y);
                if (TN == 8) {
                    double2 bq1 = Br[1];
                    bp[2] = __double_as_longlong(bq1.x);
                    bp[3] = __double_as_longlong(bq1.y);
                }
            }
#pragma unroll
            for (int i = 0; i < TM; i++)
#pragma unroll
                for (int j = 0; j < TN2; j++)
                    acc2[i][j] = fma2(ad[i], bp[j], acc2[i][j]);
        }
        __syncthreads();
    }

#pragma unroll
    for (int i = 0; i < TM; i++) {
        int gm = m0 + ty * TM + i;
        if (gm >= M) continue;
        float accs[TN];
#pragma unroll
        for (int j = 0; j < TN2; j++) unpack2(acc2[i][j], accs[2 * j], accs[2 * j + 1]);
        if (MODE == 2) {
            float4 a0 = *reinterpret_cast<const float4*>(g_agg0 + (size_t)gm * OO + tx * 4);
            float4 a1 = *reinterpret_cast<const float4*>(g_agg1 + (size_t)gm * OO + tx * 4);
            float4 o;
            o.x = accs[0] + g_b2[tx * 4 + 0] + a0.x + a1.x;
            o.y = accs[1] + g_b2[tx * 4 + 1] + a0.y + a1.y;
            o.z = accs[2] + g_b2[tx * 4 + 2] + a0.z + a1.z;
            o.w = accs[3] + g_b2[tx * 4 + 3] + a0.w + a1.w;
            *reinterpret_cast<float4*>(g_h2 + (size_t)gm * OO + tx * 4) = o;
        } else {
#pragma unroll
            for (int j = 0; j < TN; j++) {
                int gn = tx * TN + j;
                float v = accs[j];
                if (MODE == 1) v = fmaxf(v + g_b1[gn], 0.f);
                C[(size_t)gm * N + gn] = v;
            }
        }
    }
}

// ---------------- edge scoring (16 lanes per edge, float4) ------------------
__global__ void score_kernel(const int* __restrict__ edges,
                             const int* __restrict__ neg,
                             float* __restrict__ out, int out_n) {
    int t = blockIdx.x * blockDim.x + threadIdx.x;
    int ge = t >> 4;
    int lane = t & 15;
    if (ge >= 2 * EE) return;
    int u, v;
    if (ge < EE) { u = edges[ge]; v = edges[EE + ge]; }
    else { int e = ge - EE; u = neg[e]; v = neg[EE + e]; }
    float4 a = *reinterpret_cast<const float4*>(g_h2 + (size_t)u * OO + lane * 4);
    float4 b = *reinterpret_cast<const float4*>(g_h2 + (size_t)v * OO + lane * 4);
    float s = a.x * b.x + a.y * b.y + a.z * b.z + a.w * b.w;
#pragma unroll
    for (int off = 8; off; off >>= 1) s += __shfl_xor_sync(0xffffffffu, s, off);
    if (lane == 0 && ge < out_n) out[ge] = s;
}

// ---------------- launch ----------------------------------------------------
extern "C" void kernel_launch(void* const* d_in, const int* in_sizes, int n_in,
                              void* d_out, int out_size) {
    // Resolve inputs by element count; positional fallback (reference order).
    const float* x = nullptr;  const int* edges = nullptr; const int* neg = nullptr;
    const float* Wneigh1 = nullptr, *Wself1 = nullptr, *b1 = nullptr;
    const float* Wneigh2 = nullptr, *Wself2 = nullptr, *b2 = nullptr;
    {
        const float* wn1 = nullptr, *ws1 = nullptr, *wn2 = nullptr, *ws2 = nullptr;
        const float* xx = nullptr, *bb1 = nullptr, *bb2 = nullptr;
        const int* ee = nullptr, *nn = nullptr;
        for (int i = 0; i < n_in; ++i) {
            long s = in_sizes[i];
            const void* p = d_in[i];
            if      (s == (long)NN * FF)       xx = (const float*)p;
            else if (s == (long)2 * 2 * EE)    ee = (const int*)p;
            else if (s == (long)2 * EE)        nn = (const int*)p;
            else if (s == (long)2 * 128 * 128) { if (!wn1) wn1 = (const float*)p; else ws1 = (const float*)p; }
            else if (s == (long)2 * 128)       bb1 = (const float*)p;
            else if (s == (long)2 * 128 * 64)  { if (!wn2) wn2 = (const float*)p; else ws2 = (const float*)p; }
            else if (s == (long)2 * 64)        bb2 = (const float*)p;
        }
        if (xx && ee && nn && wn1 && ws1 && bb1 && wn2 && ws2 && bb2) {
            x = xx; edges = ee; neg = nn;
            Wneigh1 = wn1; Wself1 = ws1; b1 = bb1;
            Wneigh2 = wn2; Wself2 = ws2; b2 = bb2;
        }
    }
    if (!x) {
        x       = (const float*)d_in[0];
        edges   = (const int*)  d_in[1];
        neg     = (const int*)  d_in[2];
        Wneigh1 = (const float*)d_in[3];
        Wself1  = (const float*)d_in[4];
        b1      = (const float*)d_in[5];
        Wneigh2 = (const float*)d_in[6];
        Wself2  = (const float*)d_in[7];
        b2      = (const float*)d_in[8];
    }
    float* out = (float*)d_out;
    int out_n = out_size;
    if (out_n > 2 * EE) out_n = 2 * EE;

    int edgeBlocks    = (2 * EE + 255) / 256;
    int segBlocks     = (NSEG + 255) / 256;
    int gather1Blocks = (NSEG * 32 + 255) / 256;
    int gather2Blocks = (NSEG * 16 + 255) / 256;
    int gemmBlocks    = (NN + 127) / 128;
    int scoreBlocks   = (2 * EE * 16 + 255) / 256;

    // CSR build (used by both layers)
    zero_deg_kernel<<<segBlocks, 256>>>();                                // 1
    deg_kernel<<<edgeBlocks, 256>>>(edges);                               // 2
    scanA_kernel<<<NB_SCAN, 1024>>>();                                    // 3
    scanBC_kernel<<<segBlocks, 256>>>();                                  // 4
    fill_kernel<<<edgeBlocks, 256>>>(edges);                              // 5
    gather1_kernel<<<gather1Blocks, 256>>>(x);                            // 6

    // packed weights (both layers, one launch)
    pack_all_kernel<<<(384 * 128 + 255) / 256, 256>>>(Wself1, Wneigh1, b1,
                                                      Wself2, Wneigh2, b2); // 7

    // layer 1 fused GEMM
    gemm_k<1><<<gemmBlocks, 256>>>(x);                                    // 8

    // layer 2: project-then-gather (64-wide)
    gemm_k<3><<<gemmBlocks, 256>>>(nullptr);                              // 9
    gather2_kernel<<<gather2Blocks, 256>>>();                             // 10
    gemm_k<2><<<gemmBlocks, 256>>>(nullptr);                              // 11

    // scoring
    score_kernel<<<scoreBlocks, 256>>>(edges, neg, out, out_n);           // 12
}